// round 7
// baseline (speedup 1.0000x reference)
#include <cuda_runtime.h>
#include <cstdint>

// Problem constants: B=512, T=2048, I=4, H=100, O=1
#define HDIM    100
#define TLEN    2048
#define NBATCH  2       // batch groups per CTA (each group = 4 whole warps)
#define BLOCK_T 256
#define NBLOCKS 256     // 256 * 2 = 512 batches
#define PADH    112     // padded h row (16B aligned)

// ---- packed fp32x2 ops (Blackwell FFMA2 path, only reachable via PTX) ----
__device__ __forceinline__ unsigned long long ffma2(unsigned long long a,
                                                    unsigned long long b,
                                                    unsigned long long c) {
    unsigned long long d;
    asm("fma.rn.f32x2 %0, %1, %2, %3;" : "=l"(d) : "l"(a), "l"(b), "l"(c));
    return d;
}
__device__ __forceinline__ unsigned long long fmul2(unsigned long long a,
                                                    unsigned long long b) {
    unsigned long long d;
    asm("mul.rn.f32x2 %0, %1, %2;" : "=l"(d) : "l"(a), "l"(b));
    return d;
}
__device__ __forceinline__ unsigned long long fadd2(unsigned long long a,
                                                    unsigned long long b) {
    unsigned long long d;
    asm("add.rn.f32x2 %0, %1, %2;" : "=l"(d) : "l"(a), "l"(b));
    return d;
}
__device__ __forceinline__ float hsum2(unsigned long long a) {
    unsigned int lo, hi;
    asm("mov.b64 {%0, %1}, %2;" : "=r"(lo), "=r"(hi) : "l"(a));
    return __uint_as_float(lo) + __uint_as_float(hi);
}

// tanh(x) = 1 - 2/(exp2(2*log2e*x)+1)  (validated rel_err ~1e-6 over 2048 steps)
__device__ __forceinline__ float fast_tanh(float x) {
    float e, r;
    asm("ex2.approx.f32 %0, %1;" : "=f"(e) : "f"(x * 2.8853900817779268f));
    asm("rcp.approx.f32 %0, %1;" : "=f"(r) : "f"(e + 1.0f));
    return fmaf(-2.0f, r, 1.0f);
}

// named barrier: one independent domain per batch group
__device__ __forceinline__ void group_bar(int id) {
    asm volatile("bar.sync %0, %1;" :: "r"(id), "n"(128) : "memory");
}

__global__ void __launch_bounds__(BLOCK_T, 2)
crnn_kernel(const float* __restrict__ x,      // [512, 2048, 4]
            const float* __restrict__ W_ih,   // [100, 4]
            const float* __restrict__ W_hh,   // [100, 100]
            const float* __restrict__ W_fc,   // [1, 100]
            const float* __restrict__ b_fc,   // [1]
            float* __restrict__ out)          // [512, 2048, 1]
{
    // double-buffered hidden state, one row per batch group
    __shared__ __align__(16) float hbuf[2][NBATCH][PADH];
    // 4-deep ring of per-warp output-projection partials (write t, read t+2)
    __shared__ float ppart[4][NBATCH][4];

    const int tid   = threadIdx.x;
    const int g     = tid >> 7;        // batch group 0..1
    const int hh    = tid & 127;       // h index within group; >=100 inactive
    const int wig   = (tid >> 5) & 3;  // warp index within group
    const int lane  = tid & 31;
    const bool active = (hh < HDIM);
    const int row   = active ? hh : (HDIM - 1);   // clamp for safe loads
    const int bg    = blockIdx.x * NBATCH + g;
    const int barid = 1 + g;           // named barrier id (0 left for syncthreads)

    // zero both h buffers (h0 = 0)
    for (int i = tid; i < 2 * NBATCH * PADH; i += BLOCK_T)
        ((float*)hbuf)[i] = 0.0f;

    // W_hh row -> 50 fp32x2 pairs = 100 registers (paired over K)
    unsigned long long w[50];
    {
        const ulonglong2* wrow =
            reinterpret_cast<const ulonglong2*>(W_hh + row * HDIM);
        #pragma unroll
        for (int j = 0; j < 25; j++) {
            ulonglong2 v = wrow[j];
            w[2 * j]     = v.x;
            w[2 * j + 1] = v.y;
        }
    }

    // W_ih row (4 floats) as two fp32x2 pairs
    const ulonglong2 wihv =
        *reinterpret_cast<const ulonglong2*>(W_ih + row * 4);

    const float wfc  = active ? W_fc[hh] : 0.0f;
    const float bias = b_fc[0];

    const ulonglong2* xp =
        reinterpret_cast<const ulonglong2*>(x) + (size_t)bg * TLEN;
    float* op = out + (size_t)bg * TLEN;

    __syncthreads();                   // init barrier (block-wide, once)

    ulonglong2 xcur = xp[0];

    #pragma unroll 1
    for (int t = 0; t < TLEN; t++) {
        // ---- write out[t-2] (partials published 2 steps ago; ordered by
        //      the group barrier at end of step t-1)
        if (hh == 0 && t >= 2) {
            const float* pp = ppart[(t - 2) & 3][g];
            op[t - 2] = pp[0] + pp[1] + pp[2] + pp[3] + bias;
        }

        // prefetch next timestep's x
        const int tn = (t < TLEN - 1) ? (t + 1) : t;
        ulonglong2 xnext = xp[tn];

        const int cur = t & 1;

        // accumulator init = input projection xp_t
        unsigned long long a0 = fmul2(xcur.x, wihv.x);
        a0 = ffma2(xcur.y, wihv.y, a0);
        unsigned long long a1 = 0ull, a2 = 0ull, a3 = 0ull;

        // matvec: 25x broadcast LDS.128 + 50x FFMA2 (one batch row per warp:
        // pure broadcast, conflict-free)
        const ulonglong2* hv =
            reinterpret_cast<const ulonglong2*>(&hbuf[cur][g][0]);
        #pragma unroll
        for (int j = 0; j < 25; j++) {
            ulonglong2 h4 = hv[j];
            if (j & 1) {
                a2 = ffma2(h4.x, w[2 * j], a2);
                a3 = ffma2(h4.y, w[2 * j + 1], a3);
            } else {
                a0 = ffma2(h4.x, w[2 * j], a0);
                a1 = ffma2(h4.y, w[2 * j + 1], a1);
            }
        }

        const float pre  = hsum2(fadd2(fadd2(a0, a1), fadd2(a2, a3)));
        const float hnew = fast_tanh(pre);

        if (active)
            hbuf[cur ^ 1][g][hh] = hnew;

        group_bar(barid);              // h_{t+1} published; next step may start

        // ---- output projection for step t: dead-end work, overlaps the
        //      next iteration's matvec (no dependency until read at t+2)
        float p = active ? hnew * wfc : 0.0f;
        p += __shfl_xor_sync(0xFFFFFFFFu, p, 1);
        p += __shfl_xor_sync(0xFFFFFFFFu, p, 2);
        p += __shfl_xor_sync(0xFFFFFFFFu, p, 4);
        p += __shfl_xor_sync(0xFFFFFFFFu, p, 8);
        p += __shfl_xor_sync(0xFFFFFFFFu, p, 16);
        if (lane == 0)
            ppart[t & 3][g][wig] = p;

        xcur = xnext;
    }

    // flush: partials for t = TLEN-2, TLEN-1 (order their writes first)
    group_bar(barid);
    if (hh == 0) {
        const float* p2 = ppart[(TLEN - 2) & 3][g];
        op[TLEN - 2] = p2[0] + p2[1] + p2[2] + p2[3] + bias;
        const float* p1 = ppart[(TLEN - 1) & 3][g];
        op[TLEN - 1] = p1[0] + p1[1] + p1[2] + p1[3] + bias;
    }
}

extern "C" void kernel_launch(void* const* d_in, const int* in_sizes, int n_in,
                              void* d_out, int out_size) {
    const float* x    = (const float*)d_in[0];  // [512,2048,4]
    const float* W_ih = (const float*)d_in[1];  // [100,4]
    const float* W_hh = (const float*)d_in[2];  // [100,100]
    const float* W_fc = (const float*)d_in[3];  // [1,100]
    const float* b_fc = (const float*)d_in[4];  // [1]
    float* out = (float*)d_out;                 // [512,2048,1]

    crnn_kernel<<<NBLOCKS, BLOCK_T>>>(x, W_ih, W_hh, W_fc, b_fc, out);
}

// round 8
// speedup vs baseline: 1.0485x; 1.0485x over previous
#include <cuda_runtime.h>
#include <cstdint>

// Problem constants: B=512, T=2048, I=4, H=100, O=1
#define HDIM     100
#define TLEN     2048
#define BLOCK_T  256
#define NBLOCKS  256    // 2 batches per CTA -> 512 batches
#define PADH     128    // h row stride in smem (floats); [100,104) zero pad read
#define KH       52     // columns per K-half (100 padded to 104)
#define SKEWN    64     // serial-FMA skew quantum (~256 cyc per unit)

// ---- packed fp32x2 ops (Blackwell FFMA2 path, only reachable via PTX) ----
__device__ __forceinline__ unsigned long long ffma2(unsigned long long a,
                                                    unsigned long long b,
                                                    unsigned long long c) {
    unsigned long long d;
    asm("fma.rn.f32x2 %0, %1, %2, %3;" : "=l"(d) : "l"(a), "l"(b), "l"(c));
    return d;
}
__device__ __forceinline__ unsigned long long fadd2(unsigned long long a,
                                                    unsigned long long b) {
    unsigned long long d;
    asm("add.rn.f32x2 %0, %1, %2;" : "=l"(d) : "l"(a), "l"(b));
    return d;
}
__device__ __forceinline__ float hsum2(unsigned long long a) {
    unsigned int lo, hi;
    asm("mov.b64 {%0, %1}, %2;" : "=r"(lo), "=r"(hi) : "l"(a));
    return __uint_as_float(lo) + __uint_as_float(hi);
}

// tanh(x) = 1 - 2/(exp2(2*log2e*x)+1)  (validated rel_err ~1e-6 over 2048 steps)
__device__ __forceinline__ float fast_tanh(float x) {
    float e, r;
    asm("ex2.approx.f32 %0, %1;" : "=f"(e) : "f"(x * 2.8853900817779268f));
    asm("rcp.approx.f32 %0, %1;" : "=f"(r) : "f"(e + 1.0f));
    return fmaf(-2.0f, r, 1.0f);
}

__device__ __forceinline__ void group_bar(int id) {
    asm volatile("bar.sync %0, %1;" :: "r"(id), "n"(128) : "memory");
}

__global__ void __launch_bounds__(BLOCK_T, 2)
crnn_kernel(const float* __restrict__ x,      // [512, 2048, 4]
            const float* __restrict__ W_ih,   // [100, 4]
            const float* __restrict__ W_hh,   // [100, 100]
            const float* __restrict__ W_fc,   // [1, 100]
            const float* __restrict__ b_fc,   // [1]
            float* __restrict__ out)          // [512, 2048, 1]
{
    // double-buffered hidden state, one 128-float row per batch group
    __shared__ __align__(16) float hbuf[2][2][PADH];
    // 4-deep ring of per-warp output-projection partials
    __shared__ float ppart[4][2][4];

    const int tid   = threadIdx.x;
    const int g     = tid >> 7;          // batch group 0..1
    const int s     = tid & 127;         // slot in group
    const int wig   = s >> 5;            // warp in group 0..3
    const int lane  = tid & 31;
    const int praw  = wig * 16 + (lane >> 1);   // row-pair index 0..63
    const int j     = lane & 1;                  // K-half 0/1
    const bool active = (praw < 50);
    const int pc    = active ? praw : 49;        // clamp for safe loads
    const int row0  = 2 * pc;
    const int own   = row0 + j;                  // row this thread finalizes
    const int bg    = blockIdx.x * 2 + g;
    const int barid = 1 + g;
    const int gsel  = ((blockIdx.x & 1) << 1) | g;  // skew class 0..3

    // zero h buffers (h0 = 0; pad region stays 0 forever)
    for (int i = tid; i < 2 * 2 * PADH; i += BLOCK_T)
        ((float*)hbuf)[i] = 0.0f;

    // ---- W_hh: 2 rows x 52 cols -> 104 regs as 52 fp32x2 values ----------
    // row r, cols [52j, 52j+52): base byte = 400r + 208j, 16B aligned.
    unsigned long long w0[26], w1[26];
    {
        const ulonglong2* r0p =
            reinterpret_cast<const ulonglong2*>(W_hh + row0 * HDIM + KH * j);
        const ulonglong2* r1p =
            reinterpret_cast<const ulonglong2*>(W_hh + (row0 + 1) * HDIM + KH * j);
        #pragma unroll
        for (int k = 0; k < 13; k++) {
            ulonglong2 v = r0p[k];
            w0[2 * k] = v.x;  w0[2 * k + 1] = v.y;
        }
        #pragma unroll
        for (int k = 0; k < 12; k++) {
            ulonglong2 v = r1p[k];
            w1[2 * k] = v.x;  w1[2 * k + 1] = v.y;
        }
        // last pair of row 99's upper half would read past W_hh end; the
        // matching h values are the zero pad, so zero weights are exact.
        if (pc == 49 && j == 1) {
            w1[24] = 0ull; w1[25] = 0ull;
        } else {
            ulonglong2 v = r1p[12];
            w1[24] = v.x; w1[25] = v.y;
        }
    }

    // input-projection weights for the row this thread owns
    const float4 wih = *reinterpret_cast<const float4*>(W_ih + own * 4);
    const float  wfc = active ? W_fc[own] : 0.0f;
    const float  bias = b_fc[0];

    const float4* xp4 = reinterpret_cast<const float4*>(x) + (size_t)bg * TLEN;
    float* op = out + (size_t)bg * TLEN;

    __syncthreads();                     // init barrier (block-wide, once)

    // ---- deliberate phase skew: decorrelate the 4 barrier domains per SM
    {
        float d = 1.0f;
        #pragma unroll 1
        for (int k = 0; k < gsel * SKEWN; k++)
            d = fmaf(d, 1.0000001f, 1e-7f);
        asm volatile("" :: "f"(d));      // keep the chain alive
    }

    const float* hb = &hbuf[0][g][0];    // read buffer (h_t)
    float*       hw = &hbuf[1][g][0];    // write buffer (h_{t+1})

    float4 xc = xp4[0];

    #pragma unroll 1
    for (int t = 0; t < TLEN; t++) {
        // write out[t-2]: partials ordered by the two intervening barriers
        if (s == 0 && t >= 2) {
            const float* q = ppart[(t - 2) & 3][g];
            op[t - 2] = q[0] + q[1] + q[2] + q[3] + bias;
        }

        // prefetch next x (consumed next step; L2-resident after warmup)
        const int tn = (t < TLEN - 1) ? (t + 1) : t;
        float4 xn = xp4[tn];

        // input projection for the owned row (independent of h: done early)
        float xpj = xc.x * wih.x;
        xpj = fmaf(xc.y, wih.y, xpj);
        xpj = fmaf(xc.z, wih.z, xpj);
        xpj = fmaf(xc.w, wih.w, xpj);

        // matvec over this thread's K-half: 13 LDS.128 + 52 FFMA2
        unsigned long long a00 = 0ull, a01 = 0ull, a10 = 0ull, a11 = 0ull;
        const ulonglong2* hv =
            reinterpret_cast<const ulonglong2*>(hb + KH * j);
        #pragma unroll
        for (int k = 0; k < 13; k++) {
            ulonglong2 h4 = hv[k];
            a00 = ffma2(h4.x, w0[2 * k], a00);
            a01 = ffma2(h4.y, w0[2 * k + 1], a01);
            a10 = ffma2(h4.x, w1[2 * k], a10);
            a11 = ffma2(h4.y, w1[2 * k + 1], a11);
        }

        // half-dot sums; combine with partner lane (other K-half)
        float s0 = hsum2(fadd2(a00, a01));
        float s1 = hsum2(fadd2(a10, a11));
        float u0 = s0 + __shfl_xor_sync(0xFFFFFFFFu, s0, 1);
        float u1 = s1 + __shfl_xor_sync(0xFFFFFFFFu, s1, 1);

        const float pre  = (j ? u1 : u0) + xpj;
        const float hnew = fast_tanh(pre);

        if (active)
            hw[own] = hnew;              // STS 4B, own = 32*wig+lane: linear

        group_bar(barid);                // h_{t+1} published for this group

        // output projection (dead-end; overlaps next step's matvec)
        float p = active ? hnew * wfc : 0.0f;
        p += __shfl_xor_sync(0xFFFFFFFFu, p, 1);
        p += __shfl_xor_sync(0xFFFFFFFFu, p, 2);
        p += __shfl_xor_sync(0xFFFFFFFFu, p, 4);
        p += __shfl_xor_sync(0xFFFFFFFFu, p, 8);
        p += __shfl_xor_sync(0xFFFFFFFFu, p, 16);
        if (lane == 0)
            ppart[t & 3][g][wig] = p;

        // swap read/write h buffers
        const float* tmp = hb; hb = hw; hw = (float*)tmp;
        xc = xn;
    }

    // flush last two outputs (order the final ppart writes first)
    group_bar(barid);
    if (s == 0) {
        const float* q2 = ppart[(TLEN - 2) & 3][g];
        op[TLEN - 2] = q2[0] + q2[1] + q2[2] + q2[3] + bias;
        const float* q1 = ppart[(TLEN - 1) & 3][g];
        op[TLEN - 1] = q1[0] + q1[1] + q1[2] + q1[3] + bias;
    }
}

extern "C" void kernel_launch(void* const* d_in, const int* in_sizes, int n_in,
                              void* d_out, int out_size) {
    const float* x    = (const float*)d_in[0];  // [512,2048,4]
    const float* W_ih = (const float*)d_in[1];  // [100,4]
    const float* W_hh = (const float*)d_in[2];  // [100,100]
    const float* W_fc = (const float*)d_in[3];  // [1,100]
    const float* b_fc = (const float*)d_in[4];  // [1]
    float* out = (float*)d_out;                 // [512,2048,1]

    crnn_kernel<<<NBLOCKS, BLOCK_T>>>(x, W_ih, W_hh, W_fc, b_fc, out);
}

// round 9
// speedup vs baseline: 1.2769x; 1.2178x over previous
#include <cuda_runtime.h>
#include <cstdint>

// Problem constants: B=512, T=2048, I=4, H=100, O=1
#define HDIM     100
#define TLEN     2048
#define BLOCK_T  256
#define NBLOCKS  128    // 4 batches per CTA (2 groups x 2 batches) -> 512
#define PADH     128    // h row stride in smem (floats); [100,104) zero pad
#define KH       52     // columns per K-half (100 padded to 104)

// hidden-state trajectory scratch: [b][t][100], reduced by proj_kernel
__device__ float Hs[512u * 2048u * 100u];

// ---- packed fp32x2 ops (Blackwell FFMA2 path, only reachable via PTX) ----
__device__ __forceinline__ unsigned long long ffma2(unsigned long long a,
                                                    unsigned long long b,
                                                    unsigned long long c) {
    unsigned long long d;
    asm("fma.rn.f32x2 %0, %1, %2, %3;" : "=l"(d) : "l"(a), "l"(b), "l"(c));
    return d;
}
__device__ __forceinline__ unsigned long long fadd2(unsigned long long a,
                                                    unsigned long long b) {
    unsigned long long d;
    asm("add.rn.f32x2 %0, %1, %2;" : "=l"(d) : "l"(a), "l"(b));
    return d;
}
__device__ __forceinline__ float hsum2(unsigned long long a) {
    unsigned int lo, hi;
    asm("mov.b64 {%0, %1}, %2;" : "=r"(lo), "=r"(hi) : "l"(a));
    return __uint_as_float(lo) + __uint_as_float(hi);
}

// tanh(x) = 1 - 2/(exp2(2*log2e*x)+1)  (validated rel_err ~1e-6 over 2048 steps)
__device__ __forceinline__ float fast_tanh(float x) {
    float e, r;
    asm("ex2.approx.f32 %0, %1;" : "=f"(e) : "f"(x * 2.8853900817779268f));
    asm("rcp.approx.f32 %0, %1;" : "=f"(r) : "f"(e + 1.0f));
    return fmaf(-2.0f, r, 1.0f);
}

__device__ __forceinline__ void group_bar(int id) {
    asm volatile("bar.sync %0, %1;" :: "r"(id), "n"(128) : "memory");
}

// ============================================================================
// Kernel 1: the recurrence. Each 128-thread group advances TWO batches with
// shared W_hh registers (two independent dependency chains per warp).
// ============================================================================
__global__ void __launch_bounds__(BLOCK_T)
crnn_step_kernel(const float* __restrict__ x,      // [512, 2048, 4]
                 const float* __restrict__ W_ih,   // [100, 4]
                 const float* __restrict__ W_hh)   // [100, 100]
{
    // hbuf[buf][group][local batch][PADH]
    __shared__ __align__(16) float hbuf[2][2][2][PADH];

    const int tid   = threadIdx.x;
    const int g     = tid >> 7;          // group 0..1
    const int lane  = tid & 31;
    const int wig   = (tid >> 5) & 3;    // warp in group
    const int praw  = wig * 16 + (lane >> 1);   // row-pair index 0..63
    const int j     = lane & 1;                  // K-half 0/1
    const bool active = (praw < 50);
    const int pc    = active ? praw : 49;        // clamp for safe loads
    const int row0  = 2 * pc;
    const int own   = row0 + j;                  // row this thread finalizes
    const int bg0   = blockIdx.x * 4 + g * 2;    // first batch of this group
    const int bg1   = bg0 + 1;
    const int barid = 1 + g;

    // zero h buffers (h0 = 0; pad [100,128) stays 0 forever)
    for (int i = tid; i < 2 * 2 * 2 * PADH; i += BLOCK_T)
        ((float*)hbuf)[i] = 0.0f;

    // ---- W_hh: 2 rows x 52-col half -> 104 regs (shared by both batches) --
    unsigned long long w0[26], w1[26];
    {
        const ulonglong2* r0p =
            reinterpret_cast<const ulonglong2*>(W_hh + row0 * HDIM + KH * j);
        const ulonglong2* r1p =
            reinterpret_cast<const ulonglong2*>(W_hh + (row0 + 1) * HDIM + KH * j);
        #pragma unroll
        for (int k = 0; k < 13; k++) {
            ulonglong2 v = r0p[k];
            w0[2 * k] = v.x;  w0[2 * k + 1] = v.y;
        }
        #pragma unroll
        for (int k = 0; k < 12; k++) {
            ulonglong2 v = r1p[k];
            w1[2 * k] = v.x;  w1[2 * k + 1] = v.y;
        }
        // row 99's upper half, last pair: would read past W_hh; matching h
        // values are the zero pad, so zero weights are exact.
        if (pc == 49 && j == 1) {
            w1[24] = 0ull; w1[25] = 0ull;
        } else {
            ulonglong2 v = r1p[12];
            w1[24] = v.x; w1[25] = v.y;
        }
    }

    const float4 wih = *reinterpret_cast<const float4*>(W_ih + own * 4);

    const float4* xp0 = reinterpret_cast<const float4*>(x) + (size_t)bg0 * TLEN;
    const float4* xp1 = reinterpret_cast<const float4*>(x) + (size_t)bg1 * TLEN;
    float* hs0 = Hs + (size_t)bg0 * TLEN * HDIM + own;
    float* hs1 = Hs + (size_t)bg1 * TLEN * HDIM + own;

    __syncthreads();                     // init barrier (block-wide, once)

    // small phase skew between the two groups of this CTA
    if (g == 1) {
        float d = 1.0f;
        #pragma unroll 1
        for (int k = 0; k < 64; k++)
            d = fmaf(d, 1.0000001f, 1e-7f);
        asm volatile("" :: "f"(d));
    }

    const float* hb0 = &hbuf[0][g][0][0];
    float*       hw0 = &hbuf[1][g][0][0];
    const float* hb1 = &hbuf[0][g][1][0];
    float*       hw1 = &hbuf[1][g][1][0];

    float4 xc0 = xp0[0];
    float4 xc1 = xp1[0];

    #pragma unroll 1
    for (int t = 0; t < TLEN; t++) {
        const int tn = (t < TLEN - 1) ? (t + 1) : t;
        float4 xn0 = xp0[tn];
        float4 xn1 = xp1[tn];

        // input projections (independent of h)
        float xpj0 = xc0.x * wih.x;
        xpj0 = fmaf(xc0.y, wih.y, xpj0);
        xpj0 = fmaf(xc0.z, wih.z, xpj0);
        xpj0 = fmaf(xc0.w, wih.w, xpj0);
        float xpj1 = xc1.x * wih.x;
        xpj1 = fmaf(xc1.y, wih.y, xpj1);
        xpj1 = fmaf(xc1.z, wih.z, xpj1);
        xpj1 = fmaf(xc1.w, wih.w, xpj1);

        // two interleaved matvecs over this thread's K-half
        unsigned long long a00 = 0ull, a01 = 0ull, a10 = 0ull, a11 = 0ull;
        unsigned long long b00 = 0ull, b01 = 0ull, b10 = 0ull, b11 = 0ull;
        const ulonglong2* hva =
            reinterpret_cast<const ulonglong2*>(hb0 + KH * j);
        const ulonglong2* hvb =
            reinterpret_cast<const ulonglong2*>(hb1 + KH * j);
        #pragma unroll
        for (int k = 0; k < 13; k++) {
            ulonglong2 ha = hva[k];
            ulonglong2 hbv = hvb[k];
            a00 = ffma2(ha.x,  w0[2 * k],     a00);
            b00 = ffma2(hbv.x, w0[2 * k],     b00);
            a01 = ffma2(ha.y,  w0[2 * k + 1], a01);
            b01 = ffma2(hbv.y, w0[2 * k + 1], b01);
            a10 = ffma2(ha.x,  w1[2 * k],     a10);
            b10 = ffma2(hbv.x, w1[2 * k],     b10);
            a11 = ffma2(ha.y,  w1[2 * k + 1], a11);
            b11 = ffma2(hbv.y, w1[2 * k + 1], b11);
        }

        // half-dot sums; combine with partner lane (other K-half)
        float s00 = hsum2(fadd2(a00, a01));   // batch0, row0 half
        float s01 = hsum2(fadd2(a10, a11));   // batch0, row1 half
        float s10 = hsum2(fadd2(b00, b01));   // batch1, row0 half
        float s11 = hsum2(fadd2(b10, b11));   // batch1, row1 half
        float u00 = s00 + __shfl_xor_sync(0xFFFFFFFFu, s00, 1);
        float u01 = s01 + __shfl_xor_sync(0xFFFFFFFFu, s01, 1);
        float u10 = s10 + __shfl_xor_sync(0xFFFFFFFFu, s10, 1);
        float u11 = s11 + __shfl_xor_sync(0xFFFFFFFFu, s11, 1);

        const float hn0 = fast_tanh((j ? u01 : u00) + xpj0);
        const float hn1 = fast_tanh((j ? u11 : u10) + xpj1);

        if (active) {
            hw0[own] = hn0;                 // smem for the recurrence
            hw1[own] = hn1;
            hs0[0] = hn0;                   // gmem trajectory (dead-end)
            hs1[0] = hn1;
        }
        hs0 += HDIM;
        hs1 += HDIM;

        group_bar(barid);                   // h_{t+1} published for this group

        // swap read/write buffers
        const float* tp;
        tp = hb0; hb0 = hw0; hw0 = (float*)tp;
        tp = hb1; hb1 = hw1; hw1 = (float*)tp;
        xc0 = xn0;
        xc1 = xn1;
    }
}

// ============================================================================
// Kernel 2: out[b,t] = W_fc . h[b,t] + b_fc.  Warp per (b,t), memory-bound.
// ============================================================================
#define K2_BLOCK 256
#define K2_GRID  4096

__global__ void __launch_bounds__(K2_BLOCK)
proj_kernel(const float* __restrict__ W_fc,   // [1, 100]
            const float* __restrict__ b_fc,   // [1]
            float* __restrict__ out)          // [512*2048]
{
    const int lane  = threadIdx.x & 31;
    const int warp  = blockIdx.x * (K2_BLOCK / 32) + (threadIdx.x >> 5);
    const int nwarp = K2_GRID * (K2_BLOCK / 32);

    // lanes 0..24 each own 4 consecutive W_fc entries (25*4 = 100 exactly)
    float4 wf = make_float4(0.f, 0.f, 0.f, 0.f);
    if (lane < 25)
        wf = *reinterpret_cast<const float4*>(W_fc + lane * 4);
    const float bias = b_fc[0];

    const int total = 512 * TLEN;
    for (int bt = warp; bt < total; bt += nwarp) {
        const float4* hp =
            reinterpret_cast<const float4*>(Hs + (size_t)bt * HDIM);
        float s = 0.0f;
        if (lane < 25) {
            float4 hv = hp[lane];
            s = hv.x * wf.x;
            s = fmaf(hv.y, wf.y, s);
            s = fmaf(hv.z, wf.z, s);
            s = fmaf(hv.w, wf.w, s);
        }
        s += __shfl_xor_sync(0xFFFFFFFFu, s, 1);
        s += __shfl_xor_sync(0xFFFFFFFFu, s, 2);
        s += __shfl_xor_sync(0xFFFFFFFFu, s, 4);
        s += __shfl_xor_sync(0xFFFFFFFFu, s, 8);
        s += __shfl_xor_sync(0xFFFFFFFFu, s, 16);
        if (lane == 0)
            out[bt] = s + bias;
    }
}

extern "C" void kernel_launch(void* const* d_in, const int* in_sizes, int n_in,
                              void* d_out, int out_size) {
    const float* x    = (const float*)d_in[0];  // [512,2048,4]
    const float* W_ih = (const float*)d_in[1];  // [100,4]
    const float* W_hh = (const float*)d_in[2];  // [100,100]
    const float* W_fc = (const float*)d_in[3];  // [1,100]
    const float* b_fc = (const float*)d_in[4];  // [1]
    float* out = (float*)d_out;                 // [512,2048,1]

    crnn_step_kernel<<<NBLOCKS, BLOCK_T>>>(x, W_ih, W_hh);
    proj_kernel<<<K2_GRID, K2_BLOCK>>>(W_fc, b_fc, out);
}